// round 11
// baseline (speedup 1.0000x reference)
#include <cuda_runtime.h>
#include <cstdint>

#define W_IMG 1920
#define H_IMG 1080
#define HW (W_IMG * H_IMG)
#define GRID_Y 16
#define GRID_X 16
#define GRID_L 8
#define GRID_ELEMS (GRID_Y * GRID_X * GRID_L * 12)

#define SLAB 288        // 3 xcols * 8 z * 12 coeffs
#define XCOL_STRIDE 96  // 8 z * 12

// Block: 128 threads = 128 consecutive pixels of ONE image row (grid 15 x 1080).
// Slab: per-row y-blended grid (3 x-cols) in smem; per pixel a 4-corner (x,z)
// bilinear gather from smem.
// NEW: both outputs are staged block-contiguously in smem and written to global
// with cp.async.bulk (TMA bulk store) -- removes 12 LDS + 12 STG + 9 STG
// wavefronts per warp from the L1/LSU port.

__device__ __forceinline__ uint32_t smem_u32(const void* p) {
    uint32_t a;
    asm("{ .reg .u64 t; cvta.to.shared.u64 t, %1; cvt.u32.u64 %0, t; }"
        : "=r"(a) : "l"(p));
    return a;
}

__global__ __launch_bounds__(128)
void bilateral_grid_kernel(const float* __restrict__ rgb,
                           const float* __restrict__ grids,
                           const int*   __restrict__ idx_p,
                           float* __restrict__ out)
{
    __shared__ __align__(16) float slab[SLAB];          // 1.15 KB
    __shared__ __align__(16) float stage_aff[128 * 12]; // 6144 B
    __shared__ __align__(16) float stage_res[128 * 3];  // 1536 B

    const int tid = threadIdx.x;
    const int y   = blockIdx.y;
    const int x   = blockIdx.x * 128 + tid;
    const int pix = y * W_IMG + x;

    // ---- rgb loads early; latency hides under slab build ----
    float r = __ldg(rgb + pix);
    float g = __ldg(rgb + HW + pix);
    float b = __ldg(rgb + 2 * HW + pix);

    // ---- per-row y interpolation (uniform across block) ----
    float gy = (float)y * (15.0f / 1079.0f);
    float fy = floorf(gy);
    float wy = gy - fy;
    int y0 = (int)fy;
    if (y0 > GRID_Y - 1) y0 = GRID_Y - 1;
    int y1 = min(y0 + 1, GRID_Y - 1);

    // ---- block's base grid x-column ----
    float gx_first = (float)(blockIdx.x * 128) * (15.0f / 1919.0f);
    int xc0 = (int)floorf(gx_first);

    const float* G = grids + idx_p[0] * GRID_ELEMS;

    // ---- build y-blended slab: 3 xcols x 8 z x 12 coeffs ----
    #pragma unroll
    for (int i = tid; i < SLAB; i += 128) {
        int xcol = i / XCOL_STRIDE;
        int rem  = i - xcol * XCOL_STRIDE;
        int gxc  = min(xc0 + xcol, GRID_X - 1);
        float a  = __ldg(G + ((y0 * GRID_X + gxc) * GRID_L) * 12 + rem);
        float bb = __ldg(G + ((y1 * GRID_X + gxc) * GRID_L) * 12 + rem);
        slab[i] = fmaf(wy, bb - a, a);
    }
    __syncthreads();

    // ---- per-pixel interpolation setup ----
    float gray = 0.299f * r + 0.587f * g + 0.114f * b;
    gray = fminf(fmaxf(gray, 0.0f), 1.0f);

    float gz = gray * 7.0f;
    float fz = floorf(gz);
    float wz = gz - fz;
    int z0 = (int)fz;
    if (z0 > GRID_L - 1) z0 = GRID_L - 1;
    int z1 = min(z0 + 1, GRID_L - 1);

    float gxp = (float)x * (15.0f / 1919.0f);
    float fx = floorf(gxp);
    float wx = gxp - fx;
    int x0  = (int)fx;
    int b0  = (x0 - xc0) * XCOL_STRIDE;
    int b1  = (min(x0 + 1, GRID_X - 1) - xc0) * XCOL_STRIDE;

    float owx = 1.0f - wx;
    float owz = 1.0f - wz;
    float w00 = owx * owz;
    float w01 = owx * wz;
    float w10 = wx * owz;
    float w11 = wx * wz;

    const float4* c00 = (const float4*)(slab + b0 + z0 * 12);
    const float4* c01 = (const float4*)(slab + b0 + z1 * 12);
    const float4* c10 = (const float4*)(slab + b1 + z0 * 12);
    const float4* c11 = (const float4*)(slab + b1 + z1 * 12);

    float4 a0, a1, a2;
    {
        float4 p00 = c00[0], p01 = c01[0], p10 = c10[0], p11 = c11[0];
        a0.x = w00 * p00.x + w01 * p01.x + w10 * p10.x + w11 * p11.x;
        a0.y = w00 * p00.y + w01 * p01.y + w10 * p10.y + w11 * p11.y;
        a0.z = w00 * p00.z + w01 * p01.z + w10 * p10.z + w11 * p11.z;
        a0.w = w00 * p00.w + w01 * p01.w + w10 * p10.w + w11 * p11.w;
    }
    {
        float4 p00 = c00[1], p01 = c01[1], p10 = c10[1], p11 = c11[1];
        a1.x = w00 * p00.x + w01 * p01.x + w10 * p10.x + w11 * p11.x;
        a1.y = w00 * p00.y + w01 * p01.y + w10 * p10.y + w11 * p11.y;
        a1.z = w00 * p00.z + w01 * p01.z + w10 * p10.z + w11 * p11.z;
        a1.w = w00 * p00.w + w01 * p01.w + w10 * p10.w + w11 * p11.w;
    }
    {
        float4 p00 = c00[2], p01 = c01[2], p10 = c10[2], p11 = c11[2];
        a2.x = w00 * p00.x + w01 * p01.x + w10 * p10.x + w11 * p11.x;
        a2.y = w00 * p00.y + w01 * p01.y + w10 * p10.y + w11 * p11.y;
        a2.z = w00 * p00.z + w01 * p01.z + w10 * p10.z + w11 * p11.z;
        a2.w = w00 * p00.w + w01 * p01.w + w10 * p10.w + w11 * p11.w;
    }

    // ---- stage both outputs block-contiguously in smem ----
    {
        float4* st = (float4*)(stage_aff + tid * 12);   // 48B stride: conflict-free per STS.128 phase
        st[0] = a0;
        st[1] = a1;
        st[2] = a2;

        float* sr = stage_res + tid * 3;                // stride 3 coprime with 32: conflict-free
        sr[0] = a0.x * r + a0.y * g + a0.z * b + a0.w;
        sr[1] = a1.x * r + a1.y * g + a1.z * b + a1.w;
        sr[2] = a2.x * r + a2.y * g + a2.z * b + a2.w;
    }
    __syncthreads();

    // ---- TMA bulk stores: smem -> global, off the LSU port ----
    if (tid == 0) {
        asm volatile("fence.proxy.async.shared::cta;" ::: "memory");

        const size_t pix0 = (size_t)y * W_IMG + (size_t)blockIdx.x * 128;
        float* dst_aff = out + pix0 * 12;                        // 6144B, 16B-aligned
        float* dst_res = out + (size_t)12 * HW + pix0 * 3;       // 1536B, 16B-aligned

        uint32_t s_aff = smem_u32(stage_aff);
        uint32_t s_res = smem_u32(stage_res);

        asm volatile("cp.async.bulk.global.shared::cta.bulk_group [%0], [%1], %2;"
                     :: "l"(dst_aff), "r"(s_aff), "r"(128 * 48) : "memory");
        asm volatile("cp.async.bulk.global.shared::cta.bulk_group [%0], [%1], %2;"
                     :: "l"(dst_res), "r"(s_res), "r"(128 * 12) : "memory");
        asm volatile("cp.async.bulk.commit_group;" ::: "memory");
        // Issuing thread must not exit while TMA still reads smem.
        asm volatile("cp.async.bulk.wait_group 0;" ::: "memory");
    }
}

extern "C" void kernel_launch(void* const* d_in, const int* in_sizes, int n_in,
                              void* d_out, int out_size)
{
    const float* rgb   = (const float*)d_in[0];
    const float* grids = (const float*)d_in[1];
    const int*   idx   = (const int*)d_in[2];
    float* out = (float*)d_out;

    dim3 grid(W_IMG / 128, H_IMG);
    bilateral_grid_kernel<<<grid, 128>>>(rgb, grids, idx, out);
}

// round 12
// speedup vs baseline: 1.0580x; 1.0580x over previous
#include <cuda_runtime.h>
#include <cstdint>

#define W_IMG 1920
#define H_IMG 1080
#define HW (W_IMG * H_IMG)
#define GRID_Y 16
#define GRID_X 16
#define GRID_L 8
#define GRID_ELEMS (GRID_Y * GRID_X * GRID_L * 12)

#define SLAB 288        // 3 xcols * 8 z * 12 coeffs
#define XCOL_STRIDE 96  // 8 z * 12
#define ROWS 8          // rows per block; 1080/8 = 135

// Block: 128 threads = 128 consecutive x positions, looping over 8 image rows.
// grid = (15, 135). Raw grid levels (3 y-levels x 3 x-cols) are loaded from
// global ONCE per block; each row's y-blended slab is rebuilt smem->smem
// (double-buffered). Outputs are staged in smem (double-buffered) and written
// by TMA bulk stores, overlapped with the next row's slab build. rgb for the
// next row is prefetched during the current row's compute.

__device__ __forceinline__ uint32_t smem_u32(const void* p) {
    uint32_t a;
    asm("{ .reg .u64 t; cvta.to.shared.u64 t, %1; cvt.u32.u64 %0, t; }"
        : "=r"(a) : "l"(p));
    return a;
}

__global__ __launch_bounds__(128)
void bilateral_grid_kernel(const float* __restrict__ rgb,
                           const float* __restrict__ grids,
                           const int*   __restrict__ idx_p,
                           float* __restrict__ out)
{
    __shared__ __align__(16) float raw[3 * SLAB];           // 3.4 KB
    __shared__ __align__(16) float slab[2][SLAB];           // 2.3 KB
    __shared__ __align__(16) float stage_aff[2][128 * 12];  // 12.3 KB
    __shared__ __align__(16) float stage_res[2][128 * 3];   // 3.1 KB

    const int tid   = threadIdx.x;
    const int yrow0 = blockIdx.y * ROWS;
    const int x     = blockIdx.x * 128 + tid;

    // ---- prefetch rgb for row 0 (latency hides under raw load) ----
    int pix = yrow0 * W_IMG + x;
    float r = __ldg(rgb + pix);
    float g = __ldg(rgb + HW + pix);
    float b = __ldg(rgb + 2 * HW + pix);

    // ---- band y-levels: 8 rows span <=2 cells -> levels ybase..ybase+2 ----
    float gy0 = (float)yrow0 * (15.0f / 1079.0f);
    int ybase = (int)floorf(gy0);
    if (ybase > GRID_Y - 1) ybase = GRID_Y - 1;

    // ---- block's base grid x-column ----
    float gx_first = (float)(blockIdx.x * 128) * (15.0f / 1919.0f);
    int xc0 = (int)floorf(gx_first);

    const float* G = grids + idx_p[0] * GRID_ELEMS;

    // ---- raw load: 3 y-levels x 3 x-cols, once per block ----
    #pragma unroll
    for (int i = tid; i < 3 * SLAB; i += 128) {
        int lvl  = i / SLAB;
        int rem  = i - lvl * SLAB;
        int xcol = rem / XCOL_STRIDE;
        int rem2 = rem - xcol * XCOL_STRIDE;
        int gyl  = min(ybase + lvl, GRID_Y - 1);
        int gxc  = min(xc0 + xcol, GRID_X - 1);
        raw[i] = __ldg(G + ((gyl * GRID_X + gxc) * GRID_L) * 12 + rem2);
    }

    // ---- hoisted x interpolation (row-invariant) ----
    float gxp = (float)x * (15.0f / 1919.0f);
    float fx  = floorf(gxp);
    float wx  = gxp - fx;
    float owx = 1.0f - wx;
    int x0    = (int)fx;
    int b0    = (x0 - xc0) * XCOL_STRIDE;
    int b1    = (min(x0 + 1, GRID_X - 1) - xc0) * XCOL_STRIDE;

    __syncthreads();   // raw ready

    // ---- build slab[0] for row 0 ----
    {
        float gy = (float)yrow0 * (15.0f / 1079.0f);
        float fy = floorf(gy);
        float wy = gy - fy;
        int y0 = (int)fy; if (y0 > GRID_Y - 1) y0 = GRID_Y - 1;
        int l0 = y0 - ybase;
        int l1 = min(y0 + 1, GRID_Y - 1) - ybase;
        #pragma unroll
        for (int i = tid; i < SLAB; i += 128) {
            float a = raw[l0 * SLAB + i];
            float c = raw[l1 * SLAB + i];
            slab[0][i] = fmaf(wy, c - a, a);
        }
    }
    __syncthreads();   // slab[0] ready

    #pragma unroll 1
    for (int rr = 0; rr < ROWS; rr++) {
        const int buf = rr & 1;
        const int y = yrow0 + rr;

        // ---- prefetch next row's rgb ----
        float rn = 0.f, gn = 0.f, bn = 0.f;
        if (rr + 1 < ROWS) {
            int pixn = (y + 1) * W_IMG + x;
            rn = __ldg(rgb + pixn);
            gn = __ldg(rgb + HW + pixn);
            bn = __ldg(rgb + 2 * HW + pixn);
        }

        // ---- compute row rr ----
        float gray = 0.299f * r + 0.587f * g + 0.114f * b;
        gray = fminf(fmaxf(gray, 0.0f), 1.0f);
        float gz = gray * 7.0f;
        float fz = floorf(gz);
        float wz = gz - fz;
        int z0 = (int)fz; if (z0 > GRID_L - 1) z0 = GRID_L - 1;
        int z1 = min(z0 + 1, GRID_L - 1);

        float owz = 1.0f - wz;
        float w00 = owx * owz;
        float w01 = owx * wz;
        float w10 = wx * owz;
        float w11 = wx * wz;

        const float* sl = slab[buf];
        const float4* c00 = (const float4*)(sl + b0 + z0 * 12);
        const float4* c01 = (const float4*)(sl + b0 + z1 * 12);
        const float4* c10 = (const float4*)(sl + b1 + z0 * 12);
        const float4* c11 = (const float4*)(sl + b1 + z1 * 12);

        float4 a0, a1, a2;
        {
            float4 p00 = c00[0], p01 = c01[0], p10 = c10[0], p11 = c11[0];
            a0.x = w00 * p00.x + w01 * p01.x + w10 * p10.x + w11 * p11.x;
            a0.y = w00 * p00.y + w01 * p01.y + w10 * p10.y + w11 * p11.y;
            a0.z = w00 * p00.z + w01 * p01.z + w10 * p10.z + w11 * p11.z;
            a0.w = w00 * p00.w + w01 * p01.w + w10 * p10.w + w11 * p11.w;
        }
        {
            float4 p00 = c00[1], p01 = c01[1], p10 = c10[1], p11 = c11[1];
            a1.x = w00 * p00.x + w01 * p01.x + w10 * p10.x + w11 * p11.x;
            a1.y = w00 * p00.y + w01 * p01.y + w10 * p10.y + w11 * p11.y;
            a1.z = w00 * p00.z + w01 * p01.z + w10 * p10.z + w11 * p11.z;
            a1.w = w00 * p00.w + w01 * p01.w + w10 * p10.w + w11 * p11.w;
        }
        {
            float4 p00 = c00[2], p01 = c01[2], p10 = c10[2], p11 = c11[2];
            a2.x = w00 * p00.x + w01 * p01.x + w10 * p10.x + w11 * p11.x;
            a2.y = w00 * p00.y + w01 * p01.y + w10 * p10.y + w11 * p11.y;
            a2.z = w00 * p00.z + w01 * p01.z + w10 * p10.z + w11 * p11.z;
            a2.w = w00 * p00.w + w01 * p01.w + w10 * p10.w + w11 * p11.w;
        }

        // ---- stage outputs ----
        {
            float4* st = (float4*)(stage_aff[buf] + tid * 12);
            st[0] = a0;
            st[1] = a1;
            st[2] = a2;
            float* sr = stage_res[buf] + tid * 3;
            sr[0] = a0.x * r + a0.y * g + a0.z * b + a0.w;
            sr[1] = a1.x * r + a1.y * g + a1.z * b + a1.w;
            sr[2] = a2.x * r + a2.y * g + a2.z * b + a2.w;
        }
        __syncthreads();   // stage[buf] complete; everyone done with slab[buf]

        // ---- TMA store row rr (overlaps next slab build) ----
        if (tid == 0) {
            asm volatile("fence.proxy.async.shared::cta;" ::: "memory");
            const size_t pix0 = (size_t)y * W_IMG + (size_t)blockIdx.x * 128;
            float* dst_aff = out + pix0 * 12;
            float* dst_res = out + (size_t)12 * HW + pix0 * 3;
            uint32_t s_aff = smem_u32(stage_aff[buf]);
            uint32_t s_res = smem_u32(stage_res[buf]);
            asm volatile("cp.async.bulk.global.shared::cta.bulk_group [%0], [%1], %2;"
                         :: "l"(dst_aff), "r"(s_aff), "r"(128 * 48) : "memory");
            asm volatile("cp.async.bulk.global.shared::cta.bulk_group [%0], [%1], %2;"
                         :: "l"(dst_res), "r"(s_res), "r"(128 * 12) : "memory");
            asm volatile("cp.async.bulk.commit_group;" ::: "memory");
            // allow this group to fly; ensure group rr-1 (other buffer) is done
            asm volatile("cp.async.bulk.wait_group 1;" ::: "memory");
        }

        // ---- build slab for row rr+1 (smem->smem) ----
        if (rr + 1 < ROWS) {
            float gyN = (float)(y + 1) * (15.0f / 1079.0f);
            float fyN = floorf(gyN);
            float wyN = gyN - fyN;
            int yN0 = (int)fyN; if (yN0 > GRID_Y - 1) yN0 = GRID_Y - 1;
            int l0 = yN0 - ybase;
            int l1 = min(yN0 + 1, GRID_Y - 1) - ybase;
            float* slN = slab[1 - buf];
            #pragma unroll
            for (int i = tid; i < SLAB; i += 128) {
                float a = raw[l0 * SLAB + i];
                float c = raw[l1 * SLAB + i];
                slN[i] = fmaf(wyN, c - a, a);
            }
        }
        __syncthreads();   // next slab ready; tid0's wait done -> stage[1-buf] reusable

        r = rn; g = gn; b = bn;
    }

    // ---- drain TMA before block exit ----
    if (tid == 0) {
        asm volatile("cp.async.bulk.wait_group 0;" ::: "memory");
    }
}

extern "C" void kernel_launch(void* const* d_in, const int* in_sizes, int n_in,
                              void* d_out, int out_size)
{
    const float* rgb   = (const float*)d_in[0];
    const float* grids = (const float*)d_in[1];
    const int*   idx   = (const int*)d_in[2];
    float* out = (float*)d_out;

    dim3 grid(W_IMG / 128, H_IMG / ROWS);
    bilateral_grid_kernel<<<grid, 128>>>(rgb, grids, idx, out);
}